// round 4
// baseline (speedup 1.0000x reference)
#include <cuda_runtime.h>

// Rules_67619965108887: fuzzy rule firing strengths.
// out[b,s,r] = (a_i * b_j) * c_k,  r = i*25 + j*5 + k, where
//   a_i = f(x[i]), b_j = f(x[5+j]), c_k = f(x[10+k]),  f(v) = (v==0)?1:v.
// Association order matches jnp.prod exactly (ascending index) -> bitwise equal.
//
// R4: previous round was latency-bound (occ 34%, issue 39%) with grid=512.
// Keep the cheap phase structure (pairwise ab table + loop-invariant indices),
// halve per-CTA work: 32 positions/CTA, 256 threads, grid=1024 -> ~7 CTAs/SM,
// ~55 resident warps, shorter serial chains, more overlap.

constexpr int THREADS    = 256;
constexpr int P_PER_CTA  = 32;
constexpr int IN_VEC4    = P_PER_CTA * 15 / 4;    // 120
constexpr int OUT_VEC4   = P_PER_CTA * 125 / 4;   // 1000
constexpr int AB_STRIDE  = 32;
constexpr int N_AB       = P_PER_CTA * 25;        // 800

__global__ __launch_bounds__(THREADS, 8)
void rules_fired_kernel(const float4* __restrict__ x4,
                        float4* __restrict__ out4) {
    __shared__ float sx[P_PER_CTA * 16];          // 2 KB
    __shared__ float ab[P_PER_CTA * AB_STRIDE];   // 4 KB

    const int t = threadIdx.x;
    const size_t cta = blockIdx.x;

    // ---- Phase 1: load 32 positions' membership degrees (120 float4) ----
    if (t < IN_VEC4) {
        float4 v = x4[cta * IN_VEC4 + t];
        float vals[4] = {v.x, v.y, v.z, v.w};
        const int li0 = t * 4;
        #pragma unroll
        for (int e = 0; e < 4; e++) {
            const int li = li0 + e;               // 0..479
            const int p  = li / 15;
            const int f  = li - p * 15;
            const float w = vals[e];
            sx[p * 16 + f] = (w == 0.0f) ? 1.0f : w;
        }
    }
    __syncthreads();

    // ---- Phase 2: pairwise products ab[p][i*5+j] = a_i * b_j (800 items) ----
    #pragma unroll
    for (int k = 0; k < 4; k++) {
        const int id = t + k * THREADS;
        if (id < N_AB) {
            const int p   = id / 25;
            const int idx = id - p * 25;          // i*5 + j
            const int i   = idx / 5;
            const int j   = idx - i * 5;
            ab[p * AB_STRIDE + idx] = sx[p * 16 + i] * sx[p * 16 + 5 + j];
        }
    }
    __syncthreads();

    // ---- Phase 3: two 128-lane groups, 125 active lanes each.
    // A group covers a 4-position block (125 float4) per iteration; the lane's
    // intra-block decomposition is loop-invariant.
    const int g    = t >> 7;                      // group 0/1
    const int lane = t & 127;
    if (lane < 125) {
        int p_loc[4], ab_off[4], c_off[4];
        #pragma unroll
        for (int e = 0; e < 4; e++) {
            const int li = lane * 4 + e;          // 0..499 within a 4-pos block
            const int p  = li / 125;
            const int rr = li - p * 125;          // rule index r
            const int ij = rr / 5;                // i*5 + j
            const int k  = rr - ij * 5;
            p_loc[e]  = p;
            ab_off[e] = ij;
            c_off[e]  = 10 + k;
        }
        #pragma unroll
        for (int it = 0; it < 4; it++) {
            const int blk   = it * 2 + g;         // 0..7
            const int pbase = blk * 4;            // first position of block
            float r[4];
            #pragma unroll
            for (int e = 0; e < 4; e++) {
                const int p = pbase + p_loc[e];
                r[e] = ab[p * AB_STRIDE + ab_off[e]] * sx[p * 16 + c_off[e]];
            }
            out4[cta * OUT_VEC4 + (size_t)blk * 125 + lane] =
                make_float4(r[0], r[1], r[2], r[3]);
        }
    }
}

extern "C" void kernel_launch(void* const* d_in, const int* in_sizes, int n_in,
                              void* d_out, int out_size) {
    const float4* x4 = (const float4*)d_in[0];   // (B,S,15) float32, B*S=32768
    // d_in[1] = active_rules (compile-time structure), d_in[2] = epoch
    float4* out4 = (float4*)d_out;               // (B,S,125) float32

    const int total_pos = in_sizes[0] / 15;      // 32768
    const int n_ctas = total_pos / P_PER_CTA;    // 1024

    rules_fired_kernel<<<n_ctas, THREADS>>>(x4, out4);
}

// round 5
// speedup vs baseline: 1.0332x; 1.0332x over previous
#include <cuda_runtime.h>

// Rules_67619965108887: out[b,s,r] = (a_i*b_j)*c_k, r = i*25+j*5+k,
// a_i=f(x[i]), b_j=f(x[5+j]), c_k=f(x[10+k]), f(v)=(v==0)?1:v.
// Association (a*b)*c matches jnp.prod ascending order -> bitwise equal.
//
// R5: previous round was LSU-issue-bound (scalar LDS storm + STG.128 issue
// cost). Transpose the pairwise tables so the 4-position BLOCK index is the
// fastest axis: ab[ij][p_loc][blk], sc[k][p_loc][blk] (row stride 36 floats
// to spread banks). A lane's (ij,k,p_loc) are loop-invariant, so ONE LDS.128
// covers 4 consecutive blocks. Lanes own a float2 of the 500-float block
// (250/256 active), blocks processed in two 4-block halves to keep regs <=36
// so 7 CTAs/SM resident -> grid 1024 = ONE full wave (148*7=1036).

constexpr int THREADS   = 256;
constexpr int P_PER_CTA = 32;
constexpr int IN_VEC4   = P_PER_CTA * 15 / 4;     // 120
constexpr int OUT_VEC2  = P_PER_CTA * 125 / 2;    // 2000 float2 per CTA
constexpr int ROW       = 36;                     // padded row stride (floats)

__global__ __launch_bounds__(THREADS, 7)
void rules_fired_kernel(const float4* __restrict__ x4,
                        float2* __restrict__ out2) {
    __shared__ float sx[P_PER_CTA * 16];                 // 2 KB
    __shared__ __align__(16) float ab[25 * ROW];         // 3.6 KB [ij][slot]
    __shared__ __align__(16) float sc[5 * ROW];          // 720 B  [k][slot]
    // slot = p_loc*8 + blk, where position p = 4*blk + p_loc

    const int t = threadIdx.x;
    const size_t cta = blockIdx.x;

    // ---- Phase 1: load 32 positions' membership degrees (120 float4) ----
    if (t < IN_VEC4) {
        float4 v = x4[cta * IN_VEC4 + t];
        float vals[4] = {v.x, v.y, v.z, v.w};
        const int li0 = t * 4;
        #pragma unroll
        for (int e = 0; e < 4; e++) {
            const int li = li0 + e;               // 0..479
            const int p  = li / 15;
            const int f  = li - p * 15;
            const float w = vals[e];
            sx[p * 16 + f] = (w == 0.0f) ? 1.0f : w;
        }
    }
    __syncthreads();

    // ---- Phase 2: build transposed tables: 800 ab + 160 c entries ----
    #pragma unroll
    for (int q = 0; q < 4; q++) {
        const int id = t + q * THREADS;
        if (id < 800) {
            const int p    = id / 25;
            const int idx  = id - p * 25;         // ij = i*5 + j
            const int i    = idx / 5;
            const int j    = idx - i * 5;
            const int slot = (p & 3) * 8 + (p >> 2);
            ab[idx * ROW + slot] = sx[p * 16 + i] * sx[p * 16 + 5 + j];
        } else if (id < 960) {
            const int id2  = id - 800;
            const int p    = id2 / 5;
            const int k    = id2 - p * 5;
            const int slot = (p & 3) * 8 + (p >> 2);
            sc[k * ROW + slot] = sx[p * 16 + 10 + k];
        }
    }
    __syncthreads();

    // ---- Phase 3: 250 lanes own one float2 of each 500-float block ----
    const int lane = t;
    if (lane < 250) {
        // loop-invariant decomposition for the two float elements
        int base_ab[2], base_c[2];
        #pragma unroll
        for (int e = 0; e < 2; e++) {
            const int li = lane * 2 + e;          // 0..499 within a block
            const int pl = li / 125;              // position slot in block
            const int rr = li - pl * 125;         // rule index r
            const int ij = rr / 5;
            const int k  = rr - ij * 5;
            base_ab[e] = ij * ROW + pl * 8;
            base_c[e]  = k  * ROW + pl * 8;
        }
        float2* o = out2 + cta * OUT_VEC2 + lane;

        #pragma unroll
        for (int h = 0; h < 2; h++) {             // two 4-block halves
            float4 A0 = *(const float4*)&ab[base_ab[0] + h * 4];
            float4 C0 = *(const float4*)&sc[base_c[0]  + h * 4];
            float4 A1 = *(const float4*)&ab[base_ab[1] + h * 4];
            float4 C1 = *(const float4*)&sc[base_c[1]  + h * 4];
            o[(size_t)(h * 4 + 0) * 250] = make_float2(A0.x * C0.x, A1.x * C1.x);
            o[(size_t)(h * 4 + 1) * 250] = make_float2(A0.y * C0.y, A1.y * C1.y);
            o[(size_t)(h * 4 + 2) * 250] = make_float2(A0.z * C0.z, A1.z * C1.z);
            o[(size_t)(h * 4 + 3) * 250] = make_float2(A0.w * C0.w, A1.w * C1.w);
        }
    }
}

extern "C" void kernel_launch(void* const* d_in, const int* in_sizes, int n_in,
                              void* d_out, int out_size) {
    const float4* x4 = (const float4*)d_in[0];   // (B,S,15) float32, B*S=32768
    // d_in[1] = active_rules (compile-time structure), d_in[2] = epoch
    float2* out2 = (float2*)d_out;               // (B,S,125) float32

    const int total_pos = in_sizes[0] / 15;      // 32768
    const int n_ctas = total_pos / P_PER_CTA;    // 1024

    rules_fired_kernel<<<n_ctas, THREADS>>>(x4, out2);
}